// round 1
// baseline (speedup 1.0000x reference)
#include <cuda_runtime.h>
#include <cuda_bf16.h>
#include <math.h>

// FM-style predictor, collapsed:
//   s[b,:]   = data[b,:] @ embed        (B=64, F=2048, D=64)
//   dot_sum  = ||s[b,:]||^2
//   lin      = data[b,:] . bias[:,0]
//   out[b]   = sigmoid(gb + lin + dot_sum)
//
// One block per batch row. 512 threads: dq = tid%16 covers 4 embed dims as a
// float4 (D=64 -> 16 quads), chunk = tid/16 covers 64 features.

#define F_NUM 2048
#define D_DIM 64
#define BATCH 64
#define THREADS 512
#define NCHUNK 32            // THREADS/16
#define FPC 64               // F_NUM/NCHUNK features per chunk

__global__ __launch_bounds__(THREADS, 1)
void KTM_22110491640579_kernel(const float* __restrict__ data,
                               const float* __restrict__ embed,
                               const float* __restrict__ bias,
                               const float* __restrict__ gbias,
                               float* __restrict__ out) {
    __shared__ float4 sdata[THREADS];   // per-(chunk,dq) partial s quads
    __shared__ float  slin[NCHUNK];     // per-chunk partial linear term

    const int b     = blockIdx.x;
    const int tid   = threadIdx.x;
    const int dq    = tid & 15;         // which float4 of the 64-dim s vector
    const int chunk = tid >> 4;         // which 64-feature slice

    const float*  xrow = data + (size_t)b * F_NUM;
    const float4* V4   = (const float4*)embed;   // embed is [F, 64] row-major -> [F,16] float4

    float4 acc = make_float4(0.f, 0.f, 0.f, 0.f);
    float  lacc = 0.f;

    const int f0 = chunk * FPC;
    #pragma unroll 8
    for (int j = 0; j < FPC; ++j) {
        const int f = f0 + j;
        const float x = xrow[f];                 // half-warp broadcast, L1-hit
        const float4 v = V4[(size_t)f * 16 + dq]; // coalesced 256B per half-warp
        acc.x = fmaf(x, v.x, acc.x);
        acc.y = fmaf(x, v.y, acc.y);
        acc.z = fmaf(x, v.z, acc.z);
        acc.w = fmaf(x, v.w, acc.w);
        if (dq == 0) lacc = fmaf(x, bias[f], lacc);
    }

    sdata[tid] = acc;
    if (dq == 0) slin[chunk] = lacc;
    __syncthreads();

    // Tree-reduce the 32 chunk partials down to chunk 0 (per dq lane).
    #pragma unroll
    for (int s = NCHUNK / 2; s >= 1; s >>= 1) {
        if (chunk < s) {
            float4 a = sdata[chunk * 16 + dq];
            float4 c = sdata[(chunk + s) * 16 + dq];
            a.x += c.x; a.y += c.y; a.z += c.z; a.w += c.w;
            sdata[chunk * 16 + dq] = a;
            if (dq == 0) {
                if (s < NCHUNK / 2) slin[chunk] += slin[chunk + s];
                else                slin[chunk] = slin[chunk] + slin[chunk + s];
            }
        }
        __syncthreads();
    }

    // First warp: lanes 0..15 hold s quads, lane 0 holds lin. Reduce & emit.
    if (tid < 32) {
        float v = 0.f;
        if (tid < 16) {
            float4 q = sdata[tid];
            v = q.x * q.x + q.y * q.y + q.z * q.z + q.w * q.w;  // ||s||^2 partial
        }
        if (tid == 0) v += slin[0];
        #pragma unroll
        for (int off = 16; off >= 1; off >>= 1)
            v += __shfl_down_sync(0xffffffffu, v, off);
        if (tid == 0) {
            const float z = gbias[0] + v;
            out[b] = 1.0f / (1.0f + expf(-z));
        }
    }
}

extern "C" void kernel_launch(void* const* d_in, const int* in_sizes, int n_in,
                              void* d_out, int out_size) {
    const float* data  = (const float*)d_in[0];   // (64, 2048)
    const float* embed = (const float*)d_in[1];   // (2048, 64)
    const float* bias  = (const float*)d_in[2];   // (2048, 1)
    const float* gb    = (const float*)d_in[3];   // (1, 1)
    float* out = (float*)d_out;                   // (64,)
    (void)in_sizes; (void)n_in; (void)out_size;

    KTM_22110491640579_kernel<<<BATCH, THREADS>>>(data, embed, bias, gb, out);
}

// round 4
// speedup vs baseline: 1.5012x; 1.5012x over previous
#include <cuda_runtime.h>
#include <cuda_bf16.h>
#include <math.h>

// pred[b] = sigmoid(gb + data[b,:].bias + || data[b,:] @ embed ||^2)
//   (the (B,F,F) Gram double-sum collapses to the squared norm of s = x @ V)
//
// Single kernel, grid = FGC x BGC = 16 x 8 = 128 blocks, 256 threads.
// Block (fg, bg): 8 batch rows x 128 features x all 64 dims.
//   - x tile staged in smem, each embed LDG.128 feeds 8 batches (32 FMA/load)
//   - partial s[b][d] and lin[b] accumulated into device scratch via RED.ADD
//   - last block (atomic ticket) finishes: ||s||^2 + lin + gb -> sigmoid,
//     then re-zeros scratch + counter so every graph replay is identical.

#define F_NUM   2048
#define D_DIM   64
#define BATCH   64
#define THREADS 256
#define BGC     8          // batch groups (8 rows each)
#define FGC     16         // feature groups
#define FPB     128        // features per block
#define BPB     8          // batch rows per block
#define NBLOCKS (BGC * FGC)

__device__ float        g_s[BATCH][D_DIM];   // zero-init, re-zeroed by last block
__device__ float        g_lin[BATCH];
__device__ unsigned int g_counter;

__global__ __launch_bounds__(THREADS)
void KTM_22110491640579_kernel(const float* __restrict__ data,
                               const float* __restrict__ embed,
                               const float* __restrict__ bias,
                               const float* __restrict__ gbias,
                               float* __restrict__ out) {
    __shared__ float4 xs4[BPB][FPB / 4];      // 4 KB: x tile [8][128]
    __shared__ float4 red[16][16][9];         // [fs][dq][b(+pad)] ~36.9 KB
    __shared__ unsigned int s_ticket;

    const int tid = threadIdx.x;
    const int fg  = blockIdx.x;
    const int bg  = blockIdx.y;
    const int f0  = fg * FPB;
    const int b0  = bg * BPB;

    // ---- stage x tile: 8 rows x 128 floats, one float4 per thread ----
    {
        const int r = tid >> 5;       // 0..7
        const int q = tid & 31;       // 0..31
        xs4[r][q] = ((const float4*)(data + (size_t)(b0 + r) * F_NUM + f0))[q];
    }
    __syncthreads();
    const float* xs = (const float*)xs4;      // [b][f] row-major, stride 128

    // ---- main loop: dq = quad of the 64-dim s vector, fs = 8-feature slice ----
    const int dq = tid & 15;                  // 16 quads = 64 dims
    const int fs = tid >> 4;                  // 16 slices x 8 features
    const float4* V4 = ((const float4*)embed) + (size_t)f0 * 16 + dq;

    float4 acc[BPB];
    #pragma unroll
    for (int b = 0; b < BPB; ++b) acc[b] = make_float4(0.f, 0.f, 0.f, 0.f);

    #pragma unroll
    for (int j = 0; j < 8; ++j) {
        const int fl = fs * 8 + j;
        const float4 v = V4[(size_t)fl * 16];            // coalesced, L2-hot
        #pragma unroll
        for (int b = 0; b < BPB; ++b) {
            const float x = xs[b * FPB + fl];            // smem broadcast
            acc[b].x = fmaf(x, v.x, acc[b].x);
            acc[b].y = fmaf(x, v.y, acc[b].y);
            acc[b].z = fmaf(x, v.z, acc[b].z);
            acc[b].w = fmaf(x, v.w, acc[b].w);
        }
    }

    // ---- reduce over the 16 feature slices ----
    #pragma unroll
    for (int b = 0; b < BPB; ++b) red[fs][dq][b] = acc[b];
    __syncthreads();

    {
        const int combo = tid >> 1;           // 128 combos = 8 b x 16 dq
        const int half  = tid & 1;            // fs 0-7 vs 8-15
        const int bb    = combo >> 4;         // 0..7
        const int dd    = combo & 15;         // 0..15
        float4 sum = make_float4(0.f, 0.f, 0.f, 0.f);
        #pragma unroll
        for (int k = 0; k < 8; ++k) {
            const float4 p = red[half * 8 + k][dd][bb];
            sum.x += p.x; sum.y += p.y; sum.z += p.z; sum.w += p.w;
        }
        sum.x += __shfl_xor_sync(0xffffffffu, sum.x, 1);
        sum.y += __shfl_xor_sync(0xffffffffu, sum.y, 1);
        sum.z += __shfl_xor_sync(0xffffffffu, sum.z, 1);
        sum.w += __shfl_xor_sync(0xffffffffu, sum.w, 1);
        if (half == 0) {
            float* dst = &g_s[b0 + bb][dd * 4];
            atomicAdd(dst + 0, sum.x);        // RED.ADD (no return use)
            atomicAdd(dst + 1, sum.y);
            atomicAdd(dst + 2, sum.z);
            atomicAdd(dst + 3, sum.w);
        }
    }

    // ---- linear term partial: warp w handles batch row w ----
    {
        const int w    = tid >> 5;            // 0..7 -> batch row
        const int lane = tid & 31;
        float l = 0.f;
        #pragma unroll
        for (int k = 0; k < 4; ++k) {
            const int fl = lane + 32 * k;
            l = fmaf(xs[w * FPB + fl], bias[f0 + fl], l);
        }
        #pragma unroll
        for (int off = 16; off >= 1; off >>= 1)
            l += __shfl_down_sync(0xffffffffu, l, off);
        if (lane == 0) atomicAdd(&g_lin[b0 + w], l);
    }

    // ---- ticket: last block finishes ----
    __threadfence();
    __syncthreads();
    if (tid == 0) s_ticket = atomicAdd(&g_counter, 1u);
    __syncthreads();
    if (s_ticket != (unsigned)(NBLOCKS - 1)) return;

    // last block: all RED.ADDs from every block are visible (fence + atomic chain)
    {
        const int b    = tid >> 2;            // 64 batches
        const int part = tid & 3;             // 4 x 16-dim chunks
        float ss = 0.f;
        #pragma unroll
        for (int k = 0; k < 16; ++k) {
            const float v = __ldcg(&g_s[b][part * 16 + k]);
            ss = fmaf(v, v, ss);
        }
        ss += __shfl_xor_sync(0xffffffffu, ss, 1);
        ss += __shfl_xor_sync(0xffffffffu, ss, 2);
        if (part == 0) {
            const float z = __ldcg(&gbias[0]) + __ldcg(&g_lin[b]) + ss;
            out[b] = 1.0f / (1.0f + expf(-z));
            g_lin[b] = 0.f;                   // reset for next replay
        }
        #pragma unroll
        for (int k = 0; k < 16; ++k)
            g_s[b][part * 16 + k] = 0.f;      // reset for next replay
        if (tid == 0) g_counter = 0u;
    }
}

extern "C" void kernel_launch(void* const* d_in, const int* in_sizes, int n_in,
                              void* d_out, int out_size) {
    const float* data  = (const float*)d_in[0];   // (64, 2048)
    const float* embed = (const float*)d_in[1];   // (2048, 64)
    const float* bias  = (const float*)d_in[2];   // (2048, 1)
    const float* gb    = (const float*)d_in[3];   // (1, 1)
    float* out = (float*)d_out;                   // (64,)
    (void)in_sizes; (void)n_in; (void)out_size;

    dim3 grid(FGC, BGC);
    KTM_22110491640579_kernel<<<grid, THREADS>>>(data, embed, bias, gb, out);
}

// round 5
// speedup vs baseline: 1.8800x; 1.2523x over previous
#include <cuda_runtime.h>
#include <cuda_bf16.h>
#include <math.h>

// pred[b] = sigmoid(gb + data[b,:].bias + || data[b,:] @ embed ||^2)
//   (the (B,F,F) Gram double-sum collapses to the squared norm of s = x @ V)
//
// Single kernel, grid = FGC x BGC = 16 x 8 = 128 blocks (one wave), 256 thr.
// Block (fg, bg): 8 batch rows x 128 features x all 64 dims.
//   - x tile staged in smem; each embed LDG.128 feeds 8 batch rows
//   - fs-reduction done entirely with SHFL.BFLY (no smem reduce, no extra BAR)
//   - partials accumulated into device scratch via relaxed RED.ADD
//   - atom.acq_rel.gpu ticket (no __threadfence); last block finishes:
//     ||s||^2 + lin + gb -> sigmoid, writes out, re-zeros scratch + counter
//     so every graph replay is identical.

#define F_NUM   2048
#define D_DIM   64
#define BATCH   64
#define THREADS 256
#define BGC     8          // batch groups (8 rows each)
#define FGC     16         // feature groups
#define FPB     128        // features per block
#define BPB     8          // batch rows per block
#define NBLOCKS (BGC * FGC)

__device__ float        g_s[BATCH][D_DIM];   // zero-init; re-zeroed by last block
__device__ float        g_lin[BATCH];
__device__ unsigned int g_counter;

__global__ __launch_bounds__(THREADS, 1)
void KTM_22110491640579_kernel(const float* __restrict__ data,
                               const float* __restrict__ embed,
                               const float* __restrict__ bias,
                               const float* __restrict__ gbias,
                               float* __restrict__ out) {
    __shared__ float4 xs4[BPB][FPB / 4];      // 4 KB x tile [8][128]
    __shared__ unsigned int s_ticket;

    const int tid  = threadIdx.x;
    const int fg   = blockIdx.x;
    const int bg   = blockIdx.y;
    const int f0   = fg * FPB;
    const int b0   = bg * BPB;
    const int w    = tid >> 5;                // warp 0..7
    const int lane = tid & 31;

    // ---- prefetch bias for the linear term (overlaps with x staging) ----
    float bv[4];
    #pragma unroll
    for (int k = 0; k < 4; ++k) bv[k] = bias[f0 + lane + 32 * k];

    // ---- stage x tile: 8 rows x 128 floats, one float4 per thread ----
    xs4[w][lane] = ((const float4*)(data + (size_t)(b0 + w) * F_NUM + f0))[lane];
    __syncthreads();
    const float* xs = (const float*)xs4;      // [b][f], stride 128

    // ---- main loop ----
    // dq = half-warp-selected quad of the 64-dim s vector (16 quads total)
    // fs = lane bits 0..3 -> 16 slices x 8 features
    const int dq = (w << 1) | (lane >> 4);    // 0..15
    const int fs = lane & 15;                 // 0..15
    const float4* V4 = ((const float4*)embed) + ((size_t)(f0 + fs * 8) * 16 + dq);

    float4 acc[BPB];
    #pragma unroll
    for (int b = 0; b < BPB; ++b) acc[b] = make_float4(0.f, 0.f, 0.f, 0.f);

    #pragma unroll
    for (int j = 0; j < 8; ++j) {
        const float4 v = V4[(size_t)j * 16];          // coalesced, L2-hot
        #pragma unroll
        for (int b = 0; b < BPB; ++b) {
            const float x = xs[b * FPB + fs * 8 + j]; // smem broadcast
            acc[b].x = fmaf(x, v.x, acc[b].x);
            acc[b].y = fmaf(x, v.y, acc[b].y);
            acc[b].z = fmaf(x, v.z, acc[b].z);
            acc[b].w = fmaf(x, v.w, acc[b].w);
        }
    }

    // ---- linear term: warp w handles batch row w, full-warp shfl reduce ----
    {
        float l = 0.f;
        #pragma unroll
        for (int k = 0; k < 4; ++k)
            l = fmaf(xs[w * FPB + lane + 32 * k], bv[k], l);
        #pragma unroll
        for (int off = 16; off >= 1; off >>= 1)
            l += __shfl_down_sync(0xffffffffu, l, off);
        if (lane == 0) atomicAdd(&g_lin[b0 + w], l);  // relaxed RED.ADD
    }

    // ---- butterfly-reduce acc over fs (lane bits 0..3); dq bit untouched ----
    #pragma unroll
    for (int off = 1; off < 16; off <<= 1) {
        #pragma unroll
        for (int b = 0; b < BPB; ++b) {
            acc[b].x += __shfl_xor_sync(0xffffffffu, acc[b].x, off);
            acc[b].y += __shfl_xor_sync(0xffffffffu, acc[b].y, off);
            acc[b].z += __shfl_xor_sync(0xffffffffu, acc[b].z, off);
            acc[b].w += __shfl_xor_sync(0xffffffffu, acc[b].w, off);
        }
    }
    // every lane now holds the full fs-sum for its dq; 8 lanes per half-warp
    // each emit one batch row's quad (parallel REDs).
    if (fs < BPB) {
        const float4 a = acc[fs];
        float* dst = &g_s[b0 + fs][dq * 4];
        atomicAdd(dst + 0, a.x);
        atomicAdd(dst + 1, a.y);
        atomicAdd(dst + 2, a.z);
        atomicAdd(dst + 3, a.w);
    }

    // ---- acq_rel ticket: no threadfence needed ----
    __syncthreads();
    if (tid == 0) {
        unsigned int old;
        asm volatile("atom.acq_rel.gpu.global.add.u32 %0, [%1], 1;"
                     : "=r"(old) : "l"(&g_counter) : "memory");
        s_ticket = old;
    }
    __syncthreads();
    if (s_ticket != (unsigned)(NBLOCKS - 1)) return;

    // ---- last block: finish + reset scratch for the next graph replay ----
    {
        const int b    = tid >> 2;            // 64 batches
        const int part = tid & 3;             // 4 x 16-dim chunks
        const float4* sv = ((const float4*)g_s[b]) + part * 4;
        float ss = 0.f;
        #pragma unroll
        for (int k = 0; k < 4; ++k) {
            const float4 v = __ldcg(sv + k);
            ss = fmaf(v.x, v.x, ss);
            ss = fmaf(v.y, v.y, ss);
            ss = fmaf(v.z, v.z, ss);
            ss = fmaf(v.w, v.w, ss);
        }
        ss += __shfl_xor_sync(0xffffffffu, ss, 1);
        ss += __shfl_xor_sync(0xffffffffu, ss, 2);
        if (part == 0) {
            const float z = __ldcg(&gbias[0]) + __ldcg(&g_lin[b]) + ss;
            out[b] = 1.0f / (1.0f + __expf(-z));
            g_lin[b] = 0.f;
        }
        const float4 z4 = make_float4(0.f, 0.f, 0.f, 0.f);
        float4* rst = ((float4*)g_s[b]) + part * 4;
        #pragma unroll
        for (int k = 0; k < 4; ++k) rst[k] = z4;
        if (tid == 0) g_counter = 0u;
    }
}

extern "C" void kernel_launch(void* const* d_in, const int* in_sizes, int n_in,
                              void* d_out, int out_size) {
    const float* data  = (const float*)d_in[0];   // (64, 2048)
    const float* embed = (const float*)d_in[1];   // (2048, 64)
    const float* bias  = (const float*)d_in[2];   // (2048, 1)
    const float* gb    = (const float*)d_in[3];   // (1, 1)
    float* out = (float*)d_out;                   // (64,)
    (void)in_sizes; (void)n_in; (void)out_size;

    dim3 grid(FGC, BGC);
    KTM_22110491640579_kernel<<<grid, THREADS>>>(data, embed, bias, gb, out);
}